// round 7
// baseline (speedup 1.0000x reference)
#include <cuda_runtime.h>
#include <cuda_bf16.h>
#include <cstdint>

#define BB 2
#define TT 2048
#define DMM 512
#define HH 8
#define DD 64
#define UU 3
#define KS 16
#define SL (TT/KS)

#define LOGU (-7.6246188f)
#define LN2  (0.6931472f)
// 0.125 * log2(e): scores carried in log2 units
#define QSCALE (0.18033688f)
#define FIXM 24.0f

// Scratch (device globals)
__device__ __align__(16) __nv_bfloat16 g_Xqh[BB*TT*DMM];
__device__ __align__(16) __nv_bfloat16 g_Xql[BB*TT*DMM];
__device__ __align__(16) __nv_bfloat16 g_Xkh[BB*TT*DMM];
__device__ __align__(16) __nv_bfloat16 g_Xkl[BB*TT*DMM];
__device__ __align__(16) __nv_bfloat16 g_Wqh[DMM*DMM];
__device__ __align__(16) __nv_bfloat16 g_Wql[DMM*DMM];
__device__ __align__(16) __nv_bfloat16 g_Wkh[DMM*DMM];
__device__ __align__(16) __nv_bfloat16 g_Wkl[DMM*DMM];
__device__ __align__(16) __nv_bfloat16 g_Qhi[BB*HH*TT*DD];
__device__ __align__(16) __nv_bfloat16 g_Qlo[BB*HH*TT*DD];
__device__ __align__(16) __nv_bfloat16 g_Khi[BB*HH*TT*DD];
__device__ __align__(16) __nv_bfloat16 g_Klo[BB*HH*TT*DD];
__device__ float g_kl[BB*HH*TT];
__device__ int   g_top[BB*HH*UU];
__device__ float g_w[BB*HH*UU*TT];
__device__ float g_part[BB*KS*HH*UU*DMM];
__device__ float g_or[BB*HH*UU*DD];

// ---------------------------------------------------------------------------
// PTX helpers
// ---------------------------------------------------------------------------
__device__ __forceinline__ uint32_t smem_u32(const void* p) {
    return (uint32_t)__cvta_generic_to_shared(p);
}
__device__ __forceinline__ void ldm4(uint32_t* r, uint32_t a) {
    asm volatile("ldmatrix.sync.aligned.m8n8.x4.shared.b16 {%0,%1,%2,%3},[%4];"
        : "=r"(r[0]), "=r"(r[1]), "=r"(r[2]), "=r"(r[3]) : "r"(a));
}
__device__ __forceinline__ void mma_bf16(float* c, const uint32_t* a,
                                         uint32_t b0, uint32_t b1) {
    asm volatile("mma.sync.aligned.m16n8k16.row.col.f32.bf16.bf16.f32 "
        "{%0,%1,%2,%3},{%4,%5,%6,%7},{%8,%9},{%0,%1,%2,%3};"
        : "+f"(c[0]), "+f"(c[1]), "+f"(c[2]), "+f"(c[3])
        : "r"(a[0]), "r"(a[1]), "r"(a[2]), "r"(a[3]), "r"(b0), "r"(b1));
}
__device__ __forceinline__ void cp16(uint32_t dst, const void* src) {
    asm volatile("cp.async.cg.shared.global [%0],[%1],16;" :: "r"(dst), "l"(src));
}
__device__ __forceinline__ void cp_commit() {
    asm volatile("cp.async.commit_group;");
}
__device__ __forceinline__ float ex2(float x) {
    float y;
    asm("ex2.approx.f32 %0,%1;" : "=f"(y) : "f"(x));
    return y;
}
__device__ __forceinline__ uint32_t pack_bf2(__nv_bfloat16 a, __nv_bfloat16 b) {
    __nv_bfloat162 t; t.x = a; t.y = b;
    return *(uint32_t*)&t;
}

// ---------------------------------------------------------------------------
// K0: split fp32 -> (hi, lo) bf16, vectorized.
// ---------------------------------------------------------------------------
__global__ __launch_bounds__(256) void split_kernel(
    const float4* __restrict__ src, uint2* __restrict__ hi,
    uint2* __restrict__ lo, int n4)
{
    int i = blockIdx.x * 256 + threadIdx.x;
    if (i >= n4) return;
    float4 v = src[i];
    __nv_bfloat16 h0 = __float2bfloat16(v.x);
    __nv_bfloat16 h1 = __float2bfloat16(v.y);
    __nv_bfloat16 h2 = __float2bfloat16(v.z);
    __nv_bfloat16 h3 = __float2bfloat16(v.w);
    __nv_bfloat16 l0 = __float2bfloat16(v.x - __bfloat162float(h0));
    __nv_bfloat16 l1 = __float2bfloat16(v.y - __bfloat162float(h1));
    __nv_bfloat16 l2 = __float2bfloat16(v.z - __bfloat162float(h2));
    __nv_bfloat16 l3 = __float2bfloat16(v.w - __bfloat162float(h3));
    uint2 uh, ul;
    uh.x = pack_bf2(h0, h1); uh.y = pack_bf2(h2, h3);
    ul.x = pack_bf2(l0, l1); ul.y = pack_bf2(l2, l3);
    hi[i] = uh;
    lo[i] = ul;
}

// ---------------------------------------------------------------------------
// K1: Q/K projection GEMM on pre-split bf16 inputs, cp.async 2-stage.
//     blockIdx.z: 0 -> Q (scale QSCALE), 1 -> K.
// ---------------------------------------------------------------------------
#define PJ_ARR 5120            // bf16 elems per [128][40] array
#define PJ_SMEM (2*4*PJ_ARR*2) // bytes = 81920

__global__ __launch_bounds__(256, 2) void proj_mma(
    const float* __restrict__ bq, const float* __restrict__ bk)
{
    extern __shared__ __nv_bfloat16 psm[];

    int which = blockIdx.z;
    const __nv_bfloat16* Ah_g = which ? g_Xkh : g_Xqh;
    const __nv_bfloat16* Al_g = which ? g_Xkl : g_Xql;
    const __nv_bfloat16* Bh_g = which ? g_Wkh : g_Wqh;
    const __nv_bfloat16* Bl_g = which ? g_Wkl : g_Wql;
    const float* bias = which ? bk : bq;

    int tid = threadIdx.x, lane = tid & 31, warp = tid >> 5;
    int wm = (warp & 3) * 32;
    int wn = (warp >> 2) * 64;
    int m0 = blockIdx.y * 128, n0 = blockIdx.x * 128;

    float acc[2][8][4];
    #pragma unroll
    for (int a = 0; a < 2; a++)
        #pragma unroll
        for (int b = 0; b < 8; b++)
            #pragma unroll
            for (int c = 0; c < 4; c++) acc[a][b][c] = 0.f;

    int arow = lane & 15, acolb = (lane >> 4) * 8;
    int brow = lane & 7,  bcolb = (lane >> 3) * 8;

    auto loadTile = [&](int it, int st) {
        int k0 = it * 32;
        #pragma unroll
        for (int rep = 0; rep < 8; rep++) {
            int idx = rep * 256 + tid;
            int a = idx >> 9;
            int r = (idx >> 2) & 127;
            int c4 = idx & 3;
            const __nv_bfloat16* base =
                (a == 0) ? Ah_g : (a == 1) ? Al_g : (a == 2) ? Bh_g : Bl_g;
            int grow = ((a < 2) ? m0 : n0) + r;
            cp16(smem_u32(psm + (st*4 + a) * PJ_ARR + r*40 + c4*8),
                 base + (size_t)grow * DMM + k0 + c4*8);
        }
        cp_commit();
    };

    loadTile(0, 0);
    loadTile(1, 1);

    for (int it = 0; it < 16; it++) {
        if (it < 15) asm volatile("cp.async.wait_group 1;");
        else         asm volatile("cp.async.wait_group 0;");
        __syncthreads();

        int st = it & 1;
        __nv_bfloat16* sAh = psm + (st*4 + 0) * PJ_ARR;
        __nv_bfloat16* sAl = psm + (st*4 + 1) * PJ_ARR;
        __nv_bfloat16* sBh = psm + (st*4 + 2) * PJ_ARR;
        __nv_bfloat16* sBl = psm + (st*4 + 3) * PJ_ARR;

        uint32_t Ah[2][2][4], Al[2][2][4];
        #pragma unroll
        for (int mf = 0; mf < 2; mf++)
            #pragma unroll
            for (int ks = 0; ks < 2; ks++) {
                ldm4(Ah[mf][ks], smem_u32(&sAh[(wm + mf*16 + arow)*40 + ks*16 + acolb]));
                ldm4(Al[mf][ks], smem_u32(&sAl[(wm + mf*16 + arow)*40 + ks*16 + acolb]));
            }
        #pragma unroll
        for (int nf = 0; nf < 8; nf++) {
            uint32_t Bh[4], Bl[4];
            ldm4(Bh, smem_u32(&sBh[(wn + nf*8 + brow)*40 + bcolb]));
            ldm4(Bl, smem_u32(&sBl[(wn + nf*8 + brow)*40 + bcolb]));
            mma_bf16(acc[0][nf], Ah[0][0], Bh[0], Bh[1]);
            mma_bf16(acc[1][nf], Ah[1][0], Bh[0], Bh[1]);
            mma_bf16(acc[0][nf], Ah[0][0], Bl[0], Bl[1]);
            mma_bf16(acc[1][nf], Ah[1][0], Bl[0], Bl[1]);
            mma_bf16(acc[0][nf], Al[0][0], Bh[0], Bh[1]);
            mma_bf16(acc[1][nf], Al[1][0], Bh[0], Bh[1]);
            mma_bf16(acc[0][nf], Ah[0][1], Bh[2], Bh[3]);
            mma_bf16(acc[1][nf], Ah[1][1], Bh[2], Bh[3]);
            mma_bf16(acc[0][nf], Ah[0][1], Bl[2], Bl[3]);
            mma_bf16(acc[1][nf], Ah[1][1], Bl[2], Bl[3]);
            mma_bf16(acc[0][nf], Al[0][1], Bh[2], Bh[3]);
            mma_bf16(acc[1][nf], Al[1][1], Bh[2], Bh[3]);
        }
        __syncthreads();
        if (it + 2 < 16) loadTile(it + 2, st);
    }

    __nv_bfloat16* Oh = which ? g_Khi : g_Qhi;
    __nv_bfloat16* Ol = which ? g_Klo : g_Qlo;
    float scale = which ? 1.0f : QSCALE;

    #pragma unroll
    for (int mf = 0; mf < 2; mf++) {
        #pragma unroll
        for (int nf = 0; nf < 8; nf++) {
            int n = n0 + wn + nf * 8 + 2 * (lane & 3);
            float b0 = bias[n], b1 = bias[n + 1];
            #pragma unroll
            for (int half = 0; half < 2; half++) {
                int m = m0 + wm + mf * 16 + (lane >> 2) + half * 8;
                int bb = m >> 11, t = m & 2047;
                int head = n >> 6, d = n & 63;
                size_t idx = (((size_t)bb * HH + head) * TT + t) * DD + d;
                float x0 = (acc[mf][nf][half*2 + 0] + b0) * scale;
                float x1 = (acc[mf][nf][half*2 + 1] + b1) * scale;
                __nv_bfloat16 h0 = __float2bfloat16(x0);
                __nv_bfloat16 h1 = __float2bfloat16(x1);
                __nv_bfloat162 ph, pl;
                ph.x = h0; ph.y = h1;
                pl.x = __float2bfloat16(x0 - __bfloat162float(h0));
                pl.y = __float2bfloat16(x1 - __bfloat162float(h1));
                *(__nv_bfloat162*)(Oh + idx) = ph;
                *(__nv_bfloat162*)(Ol + idx) = pl;
            }
        }
    }
}

// ---------------------------------------------------------------------------
// K2: fused QK^T + fixed-max softmax stats -> KL. cp.async double-buffered.
// ---------------------------------------------------------------------------
#define KLBUF (128*72)

__global__ __launch_bounds__(256, 2) void kl_mma()
{
    extern __shared__ __nv_bfloat16 dsm[];
    __nv_bfloat16* bufh0 = dsm;
    __nv_bfloat16* bufl0 = dsm + KLBUF;
    __nv_bfloat16* bufh1 = dsm + 2*KLBUF;
    __nv_bfloat16* bufl1 = dsm + 3*KLBUF;

    int tid = threadIdx.x, lane = tid & 31, warp = tid >> 5;
    int bh = blockIdx.y, q0 = blockIdx.x * 128;
    const __nv_bfloat16* Qh = g_Qhi + (size_t)bh * TT * DD;
    const __nv_bfloat16* Ql = g_Qlo + (size_t)bh * TT * DD;
    const __nv_bfloat16* Kh = g_Khi + (size_t)bh * TT * DD;
    const __nv_bfloat16* Kl = g_Klo + (size_t)bh * TT * DD;

    #pragma unroll
    for (int rep = 0; rep < 4; rep++) {
        int idx = rep * 256 + tid;
        int r = idx >> 3, c = (idx & 7) * 8;
        *(uint4*)&bufh0[r*72 + c] = *(const uint4*)(Qh + (size_t)(q0 + r) * DD + c);
        *(uint4*)&bufl0[r*72 + c] = *(const uint4*)(Ql + (size_t)(q0 + r) * DD + c);
    }
    __syncthreads();
    uint32_t Ah[4][4], Al[4][4];
    {
        int row = warp * 16 + (lane & 15);
        int colb = (lane >> 4) * 8;
        #pragma unroll
        for (int ks = 0; ks < 4; ks++) {
            ldm4(Ah[ks], smem_u32(&bufh0[row*72 + ks*16 + colb]));
            ldm4(Al[ks], smem_u32(&bufl0[row*72 + ks*16 + colb]));
        }
    }
    __syncthreads();

    auto issueK = [&](int kb, int b) {
        __nv_bfloat16* dh = b ? bufh1 : bufh0;
        __nv_bfloat16* dl = b ? bufl1 : bufl0;
        #pragma unroll
        for (int rep = 0; rep < 4; rep++) {
            int idx = rep * 256 + tid;
            int r = idx >> 3, c = (idx & 7) * 8;
            cp16(smem_u32(&dh[r*72 + c]), Kh + (size_t)(kb + r) * DD + c);
            cp16(smem_u32(&dl[r*72 + c]), Kl + (size_t)(kb + r) * DD + c);
        }
        cp_commit();
    };

    issueK(0, 0);
    issueK(128, 1);

    float Z0 = 0.f, Z1 = 0.f, S0 = 0.f, S1 = 0.f;
    int brow = lane & 7, bcolb = (lane >> 3) * 8;

    for (int kt = 0; kt < 16; kt++) {
        if (kt < 14) asm volatile("cp.async.wait_group 1;");
        else         asm volatile("cp.async.wait_group 0;");
        __syncthreads();

        __nv_bfloat16* ch = (kt & 1) ? bufh1 : bufh0;
        __nv_bfloat16* cl = (kt & 1) ? bufl1 : bufl0;

        #pragma unroll
        for (int half = 0; half < 2; half++) {
            float acc[8][4];
            #pragma unroll
            for (int nf = 0; nf < 8; nf++)
                #pragma unroll
                for (int c = 0; c < 4; c++) acc[nf][c] = 0.f;

            #pragma unroll
            for (int nfp = 0; nfp < 4; nfp++) {
                int r0 = (half*8 + 2*nfp) * 8 + brow;
                int r1 = (half*8 + 2*nfp + 1) * 8 + brow;
                float* a0 = acc[2*nfp];
                float* a1 = acc[2*nfp+1];
                uint32_t B0h[4], B0l[4], B1h[4], B1l[4];
                ldm4(B0h, smem_u32(&ch[r0*72 + bcolb]));
                ldm4(B0l, smem_u32(&cl[r0*72 + bcolb]));
                ldm4(B1h, smem_u32(&ch[r1*72 + bcolb]));
                ldm4(B1l, smem_u32(&cl[r1*72 + bcolb]));
                mma_bf16(a0, Ah[0], B0h[0], B0h[1]);
                mma_bf16(a1, Ah[0], B1h[0], B1h[1]);
                mma_bf16(a0, Ah[0], B0l[0], B0l[1]);
                mma_bf16(a1, Ah[0], B1l[0], B1l[1]);
                mma_bf16(a0, Al[0], B0h[0], B0h[1]);
                mma_bf16(a1, Al[0], B1h[0], B1h[1]);
                mma_bf16(a0, Ah[1], B0h[2], B0h[3]);
                mma_bf16(a1, Ah[1], B1h[2], B1h[3]);
                mma_bf16(a0, Ah[1], B0l[2], B0l[3]);
                mma_bf16(a1, Ah[1], B1l[2], B1l[3]);
                mma_bf16(a0, Al[1], B0h[2], B0h[3]);
                mma_bf16(a1, Al[1], B1h[2], B1h[3]);
                ldm4(B0h, smem_u32(&ch[r0*72 + 32 + bcolb]));
                ldm4(B0l, smem_u32(&cl[r0*72 + 32 + bcolb]));
                ldm4(B1h, smem_u32(&ch[r1*72 + 32 + bcolb]));
                ldm4(B1l, smem_u32(&cl[r1*72 + 32 + bcolb]));
                mma_bf16(a0, Ah[2], B0h[0], B0h[1]);
                mma_bf16(a1, Ah[2], B1h[0], B1h[1]);
                mma_bf16(a0, Ah[2], B0l[0], B0l[1]);
                mma_bf16(a1, Ah[2], B1l[0], B1l[1]);
                mma_bf16(a0, Al[2], B0h[0], B0h[1]);
                mma_bf16(a1, Al[2], B1h[0], B1h[1]);
                mma_bf16(a0, Ah[3], B0h[2], B0h[3]);
                mma_bf16(a1, Ah[3], B1h[2], B1h[3]);
                mma_bf16(a0, Ah[3], B0l[2], B0l[3]);
                mma_bf16(a1, Ah[3], B1l[2], B1l[3]);
                mma_bf16(a0, Al[3], B0h[2], B0h[3]);
                mma_bf16(a1, Al[3], B1h[2], B1h[3]);
            }

            if (half == 1) {
                __syncthreads();
                if (kt + 2 < 16) issueK((kt + 2) * 128, kt & 1);
            }

            // fixed-max stats: e = 2^(v - FIXM); Z += e; S += v*e
            #pragma unroll
            for (int nf = 0; nf < 8; nf++) {
                float v0 = acc[nf][0], v1 = acc[nf][1];
                float v2 = acc[nf][2], v3 = acc[nf][3];
                float e0 = ex2(v0 - FIXM), e1 = ex2(v1 - FIXM);
                float e2 = ex2(v2 - FIXM), e3 = ex2(v3 - FIXM);
                Z0 += e0 + e1;
                S0 = fmaf(v0, e0, fmaf(v1, e1, S0));
                Z1 += e2 + e3;
                S1 = fmaf(v2, e2, fmaf(v3, e3, S1));
            }
        }
    }

    Z0 += __shfl_xor_sync(0xffffffffu, Z0, 1);
    Z0 += __shfl_xor_sync(0xffffffffu, Z0, 2);
    S0 += __shfl_xor_sync(0xffffffffu, S0, 1);
    S0 += __shfl_xor_sync(0xffffffffu, S0, 2);
    Z1 += __shfl_xor_sync(0xffffffffu, Z1, 1);
    Z1 += __shfl_xor_sync(0xffffffffu, Z1, 2);
    S1 += __shfl_xor_sync(0xffffffffu, S1, 1);
    S1 += __shfl_xor_sync(0xffffffffu, S1, 2);

    if ((lane & 3) == 0) {
        int r = q0 + warp * 16 + (lane >> 2);
        g_kl[(size_t)bh * TT + r] =
            LN2 * (S0 / Z0 - FIXM) - logf(Z0) - LOGU;
        g_kl[(size_t)bh * TT + r + 8] =
            LN2 * (S1 / Z1 - FIXM) - logf(Z1) - LOGU;
    }
}

// ---------------------------------------------------------------------------
// K3: top-3 per (b,h)
// ---------------------------------------------------------------------------
__global__ __launch_bounds__(256) void topk_kernel()
{
    __shared__ float sv[256];
    __shared__ int   si[256];
    int bh = blockIdx.x;
    int tid = threadIdx.x;
    const float* kl = g_kl + (size_t)bh * TT;

    float v[8];
    #pragma unroll
    for (int i = 0; i < 8; i++) v[i] = kl[tid + i * 256];

    int p0 = -1, p1 = -1, p2 = -1;
    for (int r = 0; r < UU; r++) {
        float bv = -1e38f;
        int   bi = TT;
        #pragma unroll
        for (int i = 0; i < 8; i++) {
            int t = tid + i * 256;
            if (t == p0 || t == p1 || t == p2) continue;
            if (v[i] > bv) { bv = v[i]; bi = t; }
        }
        sv[tid] = bv; si[tid] = bi;
        __syncthreads();
        for (int s = 128; s > 0; s >>= 1) {
            if (tid < s) {
                float ov = sv[tid + s]; int oi = si[tid + s];
                if (ov > sv[tid] || (ov == sv[tid] && oi < si[tid])) {
                    sv[tid] = ov; si[tid] = oi;
                }
            }
            __syncthreads();
        }
        int w = si[0];
        __syncthreads();
        if (r == 0) p0 = w; else if (r == 1) p1 = w; else p2 = w;
        if (tid == 0) g_top[bh * UU + r] = w;
    }
}

// ---------------------------------------------------------------------------
// K4a: normalized attention weights for selected queries (log2 units, ex2).
// ---------------------------------------------------------------------------
__global__ __launch_bounds__(512) void attn_w_kernel()
{
    __shared__ float w_s[UU][TT];
    __shared__ float q_s[UU][DD];
    __shared__ float red[512];
    __shared__ int   tk[UU];

    int bh = blockIdx.x;
    int tid = threadIdx.x;
    const __nv_bfloat16* Kh = g_Khi + (size_t)bh * TT * DD;
    const __nv_bfloat16* Kl = g_Klo + (size_t)bh * TT * DD;
    const __nv_bfloat16* Qh = g_Qhi + (size_t)bh * TT * DD;
    const __nv_bfloat16* Ql = g_Qlo + (size_t)bh * TT * DD;

    if (tid < UU) tk[tid] = g_top[bh * UU + tid];
    __syncthreads();
    if (tid < UU * DD) {
        int u = tid / DD, d = tid % DD;
        size_t qi = (size_t)tk[u] * DD + d;
        q_s[u][d] = __bfloat162float(Qh[qi]) + __bfloat162float(Ql[qi]);
    }
    __syncthreads();

    for (int k = tid; k < TT; k += 512) {
        const uint4* khp = (const uint4*)(Kh + (size_t)k * DD);
        const uint4* klp = (const uint4*)(Kl + (size_t)k * DD);
        float s0 = 0.f, s1 = 0.f, s2 = 0.f;
        #pragma unroll
        for (int c8 = 0; c8 < 8; c8++) {
            uint4 hv = khp[c8], lv = klp[c8];
            #pragma unroll
            for (int e = 0; e < 4; e++) {
                float2 fh = __bfloat1622float2(((const __nv_bfloat162*)&hv)[e]);
                float2 fl = __bfloat1622float2(((const __nv_bfloat162*)&lv)[e]);
                int d = c8 * 8 + e * 2;
                float kx = fh.x + fl.x, ky = fh.y + fl.y;
                s0 += q_s[0][d] * kx + q_s[0][d+1] * ky;
                s1 += q_s[1][d] * kx + q_s[1][d+1] * ky;
                s2 += q_s[2][d] * kx + q_s[2][d+1] * ky;
            }
        }
        // scores in log2 units; clip bound 10000*log2e
        w_s[0][k] = fminf(fmaxf(s0, -14427.f), 14427.f);
        w_s[1][k] = fminf(fmaxf(s1, -14427.f), 14427.f);
        w_s[2][k] = fminf(fmaxf(s2, -14427.f), 14427.f);
    }
    __syncthreads();

    for (int u = 0; u < UU; u++) {
        float lm = -1e38f;
        for (int k = tid; k < TT; k += 512) lm = fmaxf(lm, w_s[u][k]);
        red[tid] = lm; __syncthreads();
        for (int s = 256; s > 0; s >>= 1) {
            if (tid < s) red[tid] = fmaxf(red[tid], red[tid + s]);
            __syncthreads();
        }
        float m = red[0];
        __syncthreads();
        float ls = 0.f;
        for (int k = tid; k < TT; k += 512) {
            float e = ex2(w_s[u][k] - m);
            w_s[u][k] = e;
            ls += e;
        }
        red[tid] = ls; __syncthreads();
        for (int s = 256; s > 0; s >>= 1) {
            if (tid < s) red[tid] += red[tid + s];
            __syncthreads();
        }
        float inv = 1.0f / red[0];
        __syncthreads();
        for (int k = tid; k < TT; k += 512)
            g_w[((size_t)bh * UU + u) * TT + k] = w_s[u][k] * inv;
        __syncthreads();
    }
}

// ---------------------------------------------------------------------------
// K4b: partial w@V GEMV over k-slices.
// ---------------------------------------------------------------------------
__global__ __launch_bounds__(512) void wv_part_kernel(const float* __restrict__ value)
{
    __shared__ float w_s[HH*UU][SL];

    int ks = blockIdx.x, b = blockIdx.y;
    int tid = threadIdx.x;
    int k0 = ks * SL;

    for (int idx = tid; idx < HH*UU*SL; idx += 512) {
        int r = idx >> 7, kk = idx & (SL - 1);
        w_s[r][kk] = g_w[((size_t)(b * HH * UU + r)) * TT + k0 + kk];
    }
    __syncthreads();

    int n = tid;
    const float* V = value + ((size_t)b * TT + k0) * DMM + n;
    float acc[HH*UU];
    #pragma unroll
    for (int r = 0; r < HH*UU; r++) acc[r] = 0.f;

    for (int kk = 0; kk < SL; kk++) {
        float v = V[(size_t)kk * DMM];
        #pragma unroll
        for (int r = 0; r < HH*UU; r++) acc[r] += w_s[r][kk] * v;
    }

    float* P = g_part + ((size_t)(b * KS + ks) * HH * UU) * DMM + n;
    #pragma unroll
    for (int r = 0; r < HH*UU; r++) P[(size_t)r * DMM] = acc[r];
}

// ---------------------------------------------------------------------------
// K4c: reduce partials + fold Wv projection.
// ---------------------------------------------------------------------------
__global__ __launch_bounds__(256) void finalize_kernel(
    const float* __restrict__ Wv, const float* __restrict__ bv)
{
    __shared__ float wv_s[UU][DMM];

    int bh = blockIdx.x;
    int b = bh >> 3, h = bh & 7;
    int tid = threadIdx.x;

    for (int p = tid; p < UU * DMM; p += 256) {
        int u = p >> 9, n = p & 511;
        int r = h * UU + u;
        float a = 0.f;
        #pragma unroll
        for (int ks = 0; ks < KS; ks++)
            a += g_part[((size_t)(b * KS + ks) * HH * UU + r) * DMM + n];
        wv_s[u][n] = a;
    }
    __syncthreads();

    if (tid < UU * DD) {
        int u = tid / DD, d = tid % DD;
        const float* wr = Wv + (size_t)(h * DD + d) * DMM;
        float a = bv[h * DD + d];
        #pragma unroll 8
        for (int n = 0; n < DMM; n++) a += wv_s[u][n] * wr[n];
        g_or[((size_t)bh * UU + u) * DD + d] = a;
    }
}

// ---------------------------------------------------------------------------
// K5: output rows.
// ---------------------------------------------------------------------------
__global__ __launch_bounds__(128) void output_kernel(
    const float* __restrict__ Wo, const float* __restrict__ bo,
    float* __restrict__ out)
{
    int bt = blockIdx.x;
    int b  = bt >> 11;
    int t  = bt & 2047;
    int n  = threadIdx.x * 4;

    float4 acc = *(const float4*)(bo + n);

    #pragma unroll
    for (int hu = 0; hu < HH * UU; hu++) {
        if (g_top[b * HH * UU + hu] == t) {
            int h = hu / UU;
            const float* orp = g_or + ((size_t)b * HH * UU + hu) * DD;
            const float* w0 = Wo + (size_t)(n + 0) * DMM + h * DD;
            const float* w1 = Wo + (size_t)(n + 1) * DMM + h * DD;
            const float* w2 = Wo + (size_t)(n + 2) * DMM + h * DD;
            const float* w3 = Wo + (size_t)(n + 3) * DMM + h * DD;
            #pragma unroll 8
            for (int d = 0; d < DD; d++) {
                float ov = orp[d];
                acc.x += ov * w0[d];
                acc.y += ov * w1[d];
                acc.z += ov * w2[d];
                acc.w += ov * w3[d];
            }
        }
    }
    *(float4*)(out + (size_t)bt * DMM + n) = acc;
}

// ---------------------------------------------------------------------------
extern "C" void kernel_launch(void* const* d_in, const int* in_sizes, int n_in,
                              void* d_out, int out_size)
{
    (void)in_sizes; (void)n_in; (void)out_size;
    const float* query = (const float*)d_in[0];
    const float* key   = (const float*)d_in[1];
    const float* value = (const float*)d_in[2];
    /* Wq */ const float* Wq = (const float*)d_in[3];
    const float* bq    = (const float*)d_in[4];
    const float* Wk    = (const float*)d_in[5];
    const float* bk    = (const float*)d_in[6];
    const float* Wv    = (const float*)d_in[7];
    const float* bv    = (const float*)d_in[8];
    const float* Wo    = (const float*)d_in[9];
    const float* bo    = (const float*)d_in[10];
    float* out = (float*)d_out;

    static bool attr_set = false;
    if (!attr_set) {
        cudaFuncSetAttribute(kl_mma, cudaFuncAttributeMaxDynamicSharedMemorySize,
                             4 * KLBUF * (int)sizeof(__nv_bfloat16));
        cudaFuncSetAttribute(proj_mma, cudaFuncAttributeMaxDynamicSharedMemorySize,
                             PJ_SMEM);
        attr_set = true;
    }

    // device-global targets (addresses resolved on host via symbol API is not
    // graph-safe; use kernels' direct references instead — pass via symbols)
    static __nv_bfloat16 *xqh = nullptr, *xql, *xkh, *xkl, *wqh, *wql, *wkh, *wkl;
    if (!xqh) {
        cudaGetSymbolAddress((void**)&xqh, g_Xqh);
        cudaGetSymbolAddress((void**)&xql, g_Xql);
        cudaGetSymbolAddress((void**)&xkh, g_Xkh);
        cudaGetSymbolAddress((void**)&xkl, g_Xkl);
        cudaGetSymbolAddress((void**)&wqh, g_Wqh);
        cudaGetSymbolAddress((void**)&wql, g_Wql);
        cudaGetSymbolAddress((void**)&wkh, g_Wkh);
        cudaGetSymbolAddress((void**)&wkl, g_Wkl);
    }

    int nX4 = BB*TT*DMM/4, nW4 = DMM*DMM/4;
    split_kernel<<<(nX4+255)/256, 256>>>((const float4*)query, (uint2*)xqh, (uint2*)xql, nX4);
    split_kernel<<<(nX4+255)/256, 256>>>((const float4*)key,   (uint2*)xkh, (uint2*)xkl, nX4);
    split_kernel<<<(nW4+255)/256, 256>>>((const float4*)Wq,    (uint2*)wqh, (uint2*)wql, nW4);
    split_kernel<<<(nW4+255)/256, 256>>>((const float4*)Wk,    (uint2*)wkh, (uint2*)wkl, nW4);

    proj_mma<<<dim3(4, 32, 2), 256, PJ_SMEM>>>(bq, bk);          // launch 5
    kl_mma<<<dim3(16, 16), 256, 4 * KLBUF * sizeof(__nv_bfloat16)>>>(); // launch 6 (profiled)
    topk_kernel<<<BB * HH, 256>>>();
    attn_w_kernel<<<BB * HH, 512>>>();
    wv_part_kernel<<<dim3(KS, BB), 512>>>(value);
    finalize_kernel<<<BB * HH, 256>>>(Wv, bv);
    output_kernel<<<BB * TT, 128>>>(Wo, bo, out);
}